// round 13
// baseline (speedup 1.0000x reference)
#include <cuda_runtime.h>
#include <cuda_bf16.h>
#include <math.h>
#include <stdint.h>

// ---------------- problem constants ----------------
#define BB 64
#define PP 576
#define DD 768
#define NG 64
#define NN 65
#define NSTEPS 8
#define SW 72              // padded dyn matrix stride (6 chunks x 12)
#define ROWS_PAD 4224      // 4160 rows + pad (33 x 128)
#define KTOT 1536          // [hi | lo] bf16 columns
#define NSLAB64 36         // gemm k64 slabs
#define NSLAB_G 12         // gram k64 slabs per cross-term
#define GSTRIDE 72         // smem row stride (elements)
#define TILE_ELEMS (128 * GSTRIDE)
#define NSTAGE 3
#define GEMM_SMEM (NSTAGE * 2 * TILE_ELEMS * 2)   // 110592 B

// ---------------- output layout (float32, concatenated) ----
#define OFF_KEEP  0
#define OFF_PKEEP 36928
#define OFF_GID   73792
#define OFF_GS    110656
#define OFF_DH    147520
#define OFF_QH    2581120
#define OFF_RT    4744320
#define OFF_AS    5006464
#define OFF_AST   5006465

// ---------------- scratch (static device globals) ----------
__device__ __nv_bfloat16 g_abf[ROWS_PAD * KTOT];      // 13 MB (pad rows stay 0)
__device__ __nv_bfloat16 g_bbf[DD * KTOT];            // 2.3 MB
__device__ __nv_bfloat16 g_pbf[BB * 128 * KTOT];      // 25 MB proj hi/lo, pad rows 0
__device__ float g_gramp[BB * 3 * NN * NN];
__device__ float g_gflow[BB * NG];
__device__ float g_auxsp[BB];
__device__ float g_auxst[BB];

// ---------------- helpers ----------------
__device__ __forceinline__ uint32_t smem_u32(const void* p) {
    uint32_t a;
    asm("{ .reg .u64 t; cvta.to.shared.u64 t, %1; cvt.u32.u64 %0, t; }"
        : "=r"(a) : "l"(p));
    return a;
}
__device__ __forceinline__ void ldsm_x4(uint32_t* r, uint32_t addr) {
    asm volatile("ldmatrix.sync.aligned.m8n8.x4.shared.b16 {%0,%1,%2,%3}, [%4];"
                 : "=r"(r[0]), "=r"(r[1]), "=r"(r[2]), "=r"(r[3]) : "r"(addr));
}
__device__ __forceinline__ void mma16816(float* d, const uint32_t* a,
                                         uint32_t b0, uint32_t b1) {
    asm volatile("mma.sync.aligned.m16n8k16.row.col.f32.bf16.bf16.f32 "
                 "{%0,%1,%2,%3}, {%4,%5,%6,%7}, {%8,%9}, {%0,%1,%2,%3};"
                 : "+f"(d[0]), "+f"(d[1]), "+f"(d[2]), "+f"(d[3])
                 : "r"(a[0]), "r"(a[1]), "r"(a[2]), "r"(a[3]), "r"(b0), "r"(b1));
}
__device__ __forceinline__ void cp16(uint32_t saddr, const void* g) {
    asm volatile("cp.async.cg.shared.global [%0], [%1], 16;"
                 :: "r"(saddr), "l"(g));
}
#define CP_COMMIT() asm volatile("cp.async.commit_group;" ::: "memory")
#define CP_WAIT1()  asm volatile("cp.async.wait_group 1;" ::: "memory")
#define CP_WAIT0()  asm volatile("cp.async.wait_group 0;" ::: "memory")
__device__ __forceinline__ uint32_t pkbf(__nv_bfloat16 a, __nv_bfloat16 b) {
    return (uint32_t)__bfloat16_as_ushort(a) |
           ((uint32_t)__bfloat16_as_ushort(b) << 16);
}
__device__ __forceinline__ float rcpa(float x) {
    float r; asm("rcp.approx.f32 %0, %1;" : "=f"(r) : "f"(x)); return r;
}

// ============ K1: fused group pooling + hi/lo bf16 split ==================
__global__ void k_nodes_cvt(const float* __restrict__ tokens,
                            const float* __restrict__ cls) {
    int n = blockIdx.x, b = blockIdx.y, t = threadIdx.x;
    float4 s;
    if (n == 0) {
        s = ((const float4*)&cls[b * DD])[t];
    } else {
        int g = n - 1, gr = g >> 3, gc = g & 7;
        s = make_float4(0.f, 0.f, 0.f, 0.f);
#pragma unroll
        for (int rr = 0; rr < 3; rr++)
#pragma unroll
            for (int cc = 0; cc < 3; cc++) {
                int p = (gr * 3 + rr) * 24 + gc * 3 + cc;
                float4 v = ((const float4*)&tokens[(b * PP + p) * DD])[t];
                s.x += v.x; s.y += v.y; s.z += v.z; s.w += v.w;
            }
        const float inv9 = 1.f / 9.f;
        s.x *= inv9; s.y *= inv9; s.z *= inv9; s.w *= inv9;
    }
    __nv_bfloat16 h0 = __float2bfloat16(s.x), h1 = __float2bfloat16(s.y);
    __nv_bfloat16 h2 = __float2bfloat16(s.z), h3 = __float2bfloat16(s.w);
    __nv_bfloat16 l0 = __float2bfloat16(s.x - __bfloat162float(h0));
    __nv_bfloat16 l1 = __float2bfloat16(s.y - __bfloat162float(h1));
    __nv_bfloat16 l2 = __float2bfloat16(s.z - __bfloat162float(h2));
    __nv_bfloat16 l3 = __float2bfloat16(s.w - __bfloat162float(h3));
    size_t row = (size_t)(b * NN + n);
    int col = t * 4;
    *(uint2*)&g_abf[row * KTOT + col]      = make_uint2(pkbf(h0, h1), pkbf(h2, h3));
    *(uint2*)&g_abf[row * KTOT + DD + col] = make_uint2(pkbf(l0, l1), pkbf(l2, l3));
}

// ============ K2: hi/lo bf16 split of W ===================================
__global__ void __launch_bounds__(256) k_cvtB(const float* __restrict__ Wm) {
    int lin = (blockIdx.x * 256 + threadIdx.x) * 4;   // [0, 768*768)
    int row = lin / DD, col = lin - row * DD;
    float4 v = *(const float4*)&Wm[lin];
    __nv_bfloat16 h0 = __float2bfloat16(v.x), h1 = __float2bfloat16(v.y);
    __nv_bfloat16 h2 = __float2bfloat16(v.z), h3 = __float2bfloat16(v.w);
    __nv_bfloat16 l0 = __float2bfloat16(v.x - __bfloat162float(h0));
    __nv_bfloat16 l1 = __float2bfloat16(v.y - __bfloat162float(h1));
    __nv_bfloat16 l2 = __float2bfloat16(v.z - __bfloat162float(h2));
    __nv_bfloat16 l3 = __float2bfloat16(v.w - __bfloat162float(h3));
    uint2* dh = (uint2*)&g_bbf[(size_t)row * KTOT + col];
    uint2* dl = (uint2*)&g_bbf[(size_t)row * KTOT + DD + col];
    *dh = make_uint2(pkbf(h0, h1), pkbf(h2, h3));
    *dl = make_uint2(pkbf(l0, l1), pkbf(l2, l3));
}

// ============ K3: mma.sync bf16 GEMM — epilogue emits hi/lo bf16 ==========
// grid (33, 6), block 256 (8 warps, warp tile 32x64), 3-stage cp.async.
__global__ void __launch_bounds__(256, 2) k_gemm_mma() {
    extern __shared__ __align__(16) uint16_t smem[];
    int tid = threadIdx.x, wid = tid >> 5, lane = tid & 31;
    int mbase = blockIdx.x * 128, nbase = blockIdx.y * 128;
    int wm = (wid & 3) * 32, wn = (wid >> 2) * 64;

    uint32_t base = smem_u32(smem);
    int lr[4], lc[4]; uint32_t lso[4];
#pragma unroll
    for (int i = 0; i < 4; i++) {
        int lin = tid + i * 256;
        lr[i] = lin >> 3; lc[i] = (lin & 7) * 8;
        lso[i] = (uint32_t)(lr[i] * GSTRIDE + lc[i]) * 2;
    }
    const __nv_bfloat16* gA = g_abf + (size_t)mbase * KTOT;
    const __nv_bfloat16* gB = g_bbf + (size_t)nbase * KTOT;

    auto akf = [](int s) { return (s < 12 ? s * 64 : (s < 24 ? (s - 12) * 64 : DD + (s - 24) * 64)); };
    auto bkf = [](int s) { return (s < 12 ? s * 64 : (s < 24 ? DD + (s - 12) * 64 : (s - 24) * 64)); };

    uint32_t aOff = (uint32_t)((wm + (lane & 15)) * 144 + (lane >> 4) * 16);
    uint32_t bOff = (uint32_t)((wn + (lane & 7) + ((lane >> 4) << 3)) * 144 +
                               ((lane >> 3) & 1) * 16);

#pragma unroll
    for (int p = 0; p < 2; p++) {
        int ak = akf(p), bk = bkf(p);
        uint32_t sa = base + (uint32_t)p * (2 * TILE_ELEMS * 2);
        uint32_t sb = sa + TILE_ELEMS * 2;
#pragma unroll
        for (int i = 0; i < 4; i++) {
            cp16(sa + lso[i], gA + (size_t)lr[i] * KTOT + ak + lc[i]);
            cp16(sb + lso[i], gB + (size_t)lr[i] * KTOT + bk + lc[i]);
        }
        CP_COMMIT();
    }

    float acc[2][8][4];
#pragma unroll
    for (int mi = 0; mi < 2; mi++)
#pragma unroll
        for (int nj = 0; nj < 8; nj++)
#pragma unroll
            for (int q = 0; q < 4; q++) acc[mi][nj][q] = 0.f;

    int stg = 0, stg2 = 2;
    for (int s = 0; s < NSLAB64; s++) {
        if (s < NSLAB64 - 1) CP_WAIT1(); else CP_WAIT0();
        __syncthreads();
        if (s + 2 < NSLAB64) {
            int ak = akf(s + 2), bk = bkf(s + 2);
            uint32_t sa = base + (uint32_t)stg2 * (2 * TILE_ELEMS * 2);
            uint32_t sb = sa + TILE_ELEMS * 2;
#pragma unroll
            for (int i = 0; i < 4; i++) {
                cp16(sa + lso[i], gA + (size_t)lr[i] * KTOT + ak + lc[i]);
                cp16(sb + lso[i], gB + (size_t)lr[i] * KTOT + bk + lc[i]);
            }
            CP_COMMIT();
        }
        uint32_t sa = base + (uint32_t)stg * (2 * TILE_ELEMS * 2) + aOff;
        uint32_t sb = base + (uint32_t)stg * (2 * TILE_ELEMS * 2) + TILE_ELEMS * 2 + bOff;
#pragma unroll
        for (int kk = 0; kk < 4; kk++) {
            uint32_t a[2][4], b[4][4];
#pragma unroll
            for (int mi = 0; mi < 2; mi++)
                ldsm_x4(a[mi], sa + mi * 2304 + kk * 32);
#pragma unroll
            for (int nb = 0; nb < 4; nb++)
                ldsm_x4(b[nb], sb + nb * 2304 + kk * 32);
#pragma unroll
            for (int mi = 0; mi < 2; mi++)
#pragma unroll
                for (int nj = 0; nj < 8; nj++)
                    mma16816(acc[mi][nj], a[mi],
                             b[nj >> 1][(nj & 1) * 2], b[nj >> 1][(nj & 1) * 2 + 1]);
        }
        stg = (stg == 2) ? 0 : stg + 1;
        stg2 = (stg2 == 2) ? 0 : stg2 + 1;
    }

    // epilogue: hi/lo bf16 into batch-padded g_pbf (rows 65..127 stay zero)
    int cbase = nbase + wn + (lane & 3) * 2;
#pragma unroll
    for (int mi = 0; mi < 2; mi++)
#pragma unroll
        for (int rr = 0; rr < 2; rr++) {
            int gr = mbase + wm + (lane >> 2) + mi * 16 + rr * 8;
            if (gr < BB * NN) {
                int b = gr / NN;
                int r = gr - b * NN;
                __nv_bfloat16* dst = g_pbf + (size_t)b * (128 * KTOT) + (size_t)r * KTOT;
#pragma unroll
                for (int nj = 0; nj < 8; nj++) {
                    float v0 = acc[mi][nj][rr * 2 + 0];
                    float v1 = acc[mi][nj][rr * 2 + 1];
                    __nv_bfloat16 h0 = __float2bfloat16(v0);
                    __nv_bfloat16 h1 = __float2bfloat16(v1);
                    __nv_bfloat16 l0 = __float2bfloat16(v0 - __bfloat162float(h0));
                    __nv_bfloat16 l1 = __float2bfloat16(v1 - __bfloat162float(h1));
                    int cn = cbase + nj * 8;
                    *(uint32_t*)&dst[cn]      = pkbf(h0, h1);
                    *(uint32_t*)&dst[DD + cn] = pkbf(l0, l1);
                }
            }
        }
}

// ============ K4: tensor-core Gram partials (3 cross-terms) ===============
// grid (64, 3), block 256. D = X X^T for X = g_pbf[b] with per-term K bases.
__global__ void __launch_bounds__(256, 2) k_gram_mma() {
    extern __shared__ __align__(16) uint16_t smem[];
    int tid = threadIdx.x, wid = tid >> 5, lane = tid & 31;
    int b = blockIdx.x, sterm = blockIdx.y;
    int abase = (sterm == 2) ? DD : 0;     // hh, hl, lh
    int bbase = (sterm == 1) ? DD : 0;
    int wm = (wid & 3) * 32, wn = (wid >> 2) * 64;

    uint32_t base = smem_u32(smem);
    int lr[4], lc[4]; uint32_t lso[4];
#pragma unroll
    for (int i = 0; i < 4; i++) {
        int lin = tid + i * 256;
        lr[i] = lin >> 3; lc[i] = (lin & 7) * 8;
        lso[i] = (uint32_t)(lr[i] * GSTRIDE + lc[i]) * 2;
    }
    const __nv_bfloat16* gX = g_pbf + (size_t)b * (128 * KTOT);

    uint32_t aOff = (uint32_t)((wm + (lane & 15)) * 144 + (lane >> 4) * 16);
    uint32_t bOff = (uint32_t)((wn + (lane & 7) + ((lane >> 4) << 3)) * 144 +
                               ((lane >> 3) & 1) * 16);

#pragma unroll
    for (int p = 0; p < 2; p++) {
        int ak = abase + p * 64, bk = bbase + p * 64;
        uint32_t sa = base + (uint32_t)p * (2 * TILE_ELEMS * 2);
        uint32_t sb = sa + TILE_ELEMS * 2;
#pragma unroll
        for (int i = 0; i < 4; i++) {
            cp16(sa + lso[i], gX + (size_t)lr[i] * KTOT + ak + lc[i]);
            cp16(sb + lso[i], gX + (size_t)lr[i] * KTOT + bk + lc[i]);
        }
        CP_COMMIT();
    }

    float acc[2][8][4];
#pragma unroll
    for (int mi = 0; mi < 2; mi++)
#pragma unroll
        for (int nj = 0; nj < 8; nj++)
#pragma unroll
            for (int q = 0; q < 4; q++) acc[mi][nj][q] = 0.f;

    int stg = 0, stg2 = 2;
    for (int s = 0; s < NSLAB_G; s++) {
        if (s < NSLAB_G - 1) CP_WAIT1(); else CP_WAIT0();
        __syncthreads();
        if (s + 2 < NSLAB_G) {
            int ak = abase + (s + 2) * 64, bk = bbase + (s + 2) * 64;
            uint32_t sa = base + (uint32_t)stg2 * (2 * TILE_ELEMS * 2);
            uint32_t sb = sa + TILE_ELEMS * 2;
#pragma unroll
            for (int i = 0; i < 4; i++) {
                cp16(sa + lso[i], gX + (size_t)lr[i] * KTOT + ak + lc[i]);
                cp16(sb + lso[i], gX + (size_t)lr[i] * KTOT + bk + lc[i]);
            }
            CP_COMMIT();
        }
        uint32_t sa = base + (uint32_t)stg * (2 * TILE_ELEMS * 2) + aOff;
        uint32_t sb = base + (uint32_t)stg * (2 * TILE_ELEMS * 2) + TILE_ELEMS * 2 + bOff;
#pragma unroll
        for (int kk = 0; kk < 4; kk++) {
            uint32_t a[2][4], bq[4][4];
#pragma unroll
            for (int mi = 0; mi < 2; mi++)
                ldsm_x4(a[mi], sa + mi * 2304 + kk * 32);
#pragma unroll
            for (int nb = 0; nb < 4; nb++)
                ldsm_x4(bq[nb], sb + nb * 2304 + kk * 32);
#pragma unroll
            for (int mi = 0; mi < 2; mi++)
#pragma unroll
                for (int nj = 0; nj < 8; nj++)
                    mma16816(acc[mi][nj], a[mi],
                             bq[nj >> 1][(nj & 1) * 2], bq[nj >> 1][(nj & 1) * 2 + 1]);
        }
        stg = (stg == 2) ? 0 : stg + 1;
        stg2 = (stg2 == 2) ? 0 : stg2 + 1;
    }

    // epilogue: write rows/cols < 65 into g_gramp[b][sterm]
    float* gp = &g_gramp[(size_t)(b * 3 + sterm) * (NN * NN)];
    int cb = wn + (lane & 3) * 2;
#pragma unroll
    for (int mi = 0; mi < 2; mi++)
#pragma unroll
        for (int rr = 0; rr < 2; rr++) {
            int r = wm + (lane >> 2) + mi * 16 + rr * 8;
            if (r < NN) {
#pragma unroll
                for (int nj = 0; nj < 8; nj++) {
                    int c = cb + nj * 8;
                    if (c < NN)     gp[r * NN + c]     = acc[mi][nj][rr * 2 + 0];
                    if (c + 1 < NN) gp[r * NN + c + 1] = acc[mi][nj][rr * 2 + 1];
                }
            }
        }
}

// ============ K5: C0 + dynamics — quad-pivot Gauss-Jordan =================
__global__ void __launch_bounds__(416) k_dyn(float* __restrict__ out) {
    __shared__ __align__(16) float sC[NN * SW];
    __shared__ __align__(16) float spivq[2][4][SW + 4];
    __shared__ __align__(16) float sfball[2][NN][12];
    __shared__ float sdeg[NN];
    __shared__ float sp[NN];
    __shared__ float spart[NN * 6];
    __shared__ float sdiag[NN], srhs[NN];
    __shared__ float sinv[NN];
    __shared__ float sred[512];

    int b = blockIdx.x, tid = threadIdx.x;
    int row = tid / 6, ch = tid - row * 6, c0 = ch * 12;
    bool act = (tid < 390);
    const float* gp = &g_gramp[(size_t)b * 3 * NN * NN];
    float* dh = out + OFF_DH + (size_t)b * 9 * NN * NN;
    float* qh = out + OFF_QH + (size_t)b * 8 * NN * NN;

    for (int idx = tid; idx < NN * SW; idx += 416) sC[idx] = 0.f;
    if (tid < NN) {
        int d = tid * NN + tid;
        float g = gp[d] + gp[NN * NN + d] + gp[2 * NN * NN + d];
        sinv[tid] = rsqrtf(g);
    }
    __syncthreads();
    {
        int i = tid / NN, j = tid - i * NN;
        for (int idx = tid; idx < NN * NN; idx += 416) {
            float c = 0.f;
            if (i != j) {
                float g = gp[idx] + gp[NN * NN + idx] + gp[2 * NN * NN + idx];
                float dot = g * sinv[i] * sinv[j];
                float d2 = fmaxf(2.f - 2.f * dot, 0.f);
                c = fmaxf(__expf(-d2), 1e-4f);
            }
            sC[i * SW + j] = c;
            dh[idx] = c;
            j += 26; i += 6; if (j >= NN) { j -= NN; i++; }
        }
    }
    float auxst = 0.f;

    for (int s = 0; s < NSTEPS; s++) {
        __syncthreads();
        if (act) {
            const float4* cr = (const float4*)&sC[row * SW + c0];
            float4 v0 = cr[0], v1 = cr[1], v2 = cr[2];
            spart[row * 6 + ch] = ((v0.x + v0.y) + (v0.z + v0.w))
                                + ((v1.x + v1.y) + (v1.z + v1.w))
                                + ((v2.x + v2.y) + (v2.z + v2.w));
        }
        __syncthreads();
        if (tid < NN) {
            float d = 0.f;
#pragma unroll
            for (int q = 0; q < 6; q++) d += spart[tid * 6 + q];
            sdeg[tid] = d;
        }
        __syncthreads();
        float a[12];
        if (act) {
            const float4* cr = (const float4*)&sC[row * SW + c0];
            float4 v0 = cr[0], v1 = cr[1], v2 = cr[2];
            a[0] = -v0.x; a[1] = -v0.y; a[2]  = -v0.z; a[3]  = -v0.w;
            a[4] = -v1.x; a[5] = -v1.y; a[6]  = -v1.z; a[7]  = -v1.w;
            a[8] = -v2.x; a[9] = -v2.y; a[10] = -v2.z; a[11] = -v2.w;
            if (ch == 5) a[5] = (row == 0) ? 1.f : (-1.f / 64.f);   // col 65 = rhs
            float dg = sdeg[row] + 1e-4f;
#pragma unroll
            for (int j = 0; j < 12; j++) if (c0 + j == row) a[j] = dg;
            if (ch == 0) {
                float4* fb = (float4*)&sfball[0][row][0];
                fb[0] = make_float4(a[0], a[1], a[2], a[3]);
                fb[1] = make_float4(a[4], a[5], a[6], a[7]);
                fb[2] = make_float4(a[8], a[9], a[10], a[11]);
            }
            if (row < 4) {
                float4* pv = (float4*)&spivq[0][row][c0];
                pv[0] = make_float4(a[0], a[1], a[2], a[3]);
                pv[1] = make_float4(a[4], a[5], a[6], a[7]);
                pv[2] = make_float4(a[8], a[9], a[10], a[11]);
            }
        }
        __syncthreads();
        int jk = 0, chk = 0;
        for (int t = 0; t < 16; t++) {
            int k = 4 * t;
            int pb = t & 1, nb = pb ^ 1;
            if (act) {
                float m01 = spivq[pb][0][k+1], m02 = spivq[pb][0][k+2], m03 = spivq[pb][0][k+3];
                float m10 = spivq[pb][1][k],   m11 = spivq[pb][1][k+1], m12 = spivq[pb][1][k+2], m13 = spivq[pb][1][k+3];
                float m20 = spivq[pb][2][k],   m21 = spivq[pb][2][k+1], m22 = spivq[pb][2][k+2], m23 = spivq[pb][2][k+3];
                float m30 = spivq[pb][3][k],   m31 = spivq[pb][3][k+1], m32 = spivq[pb][3][k+2], m33 = spivq[pb][3][k+3];
                float r0 = rcpa(spivq[pb][0][k]);
                float g10 = m10 * r0;
                float m11p = __fmaf_rn(-g10, m01, m11);
                float m12p = __fmaf_rn(-g10, m02, m12);
                float m13p = __fmaf_rn(-g10, m03, m13);
                float g20 = m20 * r0;
                float m21p = __fmaf_rn(-g20, m01, m21);
                float m22p = __fmaf_rn(-g20, m02, m22);
                float m23p = __fmaf_rn(-g20, m03, m23);
                float g30 = m30 * r0;
                float m31p = __fmaf_rn(-g30, m01, m31);
                float m32p = __fmaf_rn(-g30, m02, m32);
                float m33p = __fmaf_rn(-g30, m03, m33);
                float r1 = rcpa(m11p);
                float g21 = m21p * r1;
                float m22q = __fmaf_rn(-g21, m12p, m22p);
                float m23q = __fmaf_rn(-g21, m13p, m23p);
                float g31 = m31p * r1;
                float m32q = __fmaf_rn(-g31, m12p, m32p);
                float m33q = __fmaf_rn(-g31, m13p, m33p);
                float r2 = rcpa(m22q);
                float g32 = m32q * r2;
                float m33r = __fmaf_rn(-g32, m23q, m33q);
                float r3 = rcpa(m33r);
                float s0 = sfball[pb][row][jk];
                float s1 = sfball[pb][row][jk + 1];
                float s2 = sfball[pb][row][jk + 2];
                float s3 = sfball[pb][row][jk + 3];
                float f0 = (row == k) ? 0.f : s0 * r0;
                float s1p = __fmaf_rn(-f0, m01, s1);
                float f1 = (row == k + 1) ? 0.f : s1p * r1;
                float s2p = s2 - f0 * m02 - f1 * m12p;
                float f2 = (row == k + 2) ? 0.f : s2p * r2;
                float s3p = s3 - f0 * m03 - f1 * m13p - f2 * m23q;
                float f3 = (row == k + 3) ? 0.f : s3p * r3;
                float cc3 = f3;
                float cc2 = __fmaf_rn(-cc3, g32, f2);
                float cc1 = f1 - cc2 * g21 - cc3 * g31;
                float cc0 = f0 - cc1 * g10 - cc2 * g20 - cc3 * g30;
                const float4* P0 = (const float4*)&spivq[pb][0][c0];
                const float4* P1 = (const float4*)&spivq[pb][1][c0];
                const float4* P2 = (const float4*)&spivq[pb][2][c0];
                const float4* P3 = (const float4*)&spivq[pb][3][c0];
#pragma unroll
                for (int q = 0; q < 3; q++) {
                    float4 u0 = P0[q], u1 = P1[q], u2 = P2[q], u3 = P3[q];
                    a[q*4+0] -= cc0*u0.x + cc1*u1.x + cc2*u2.x + cc3*u3.x;
                    a[q*4+1] -= cc0*u0.y + cc1*u1.y + cc2*u2.y + cc3*u3.y;
                    a[q*4+2] -= cc0*u0.z + cc1*u1.z + cc2*u2.z + cc3*u3.z;
                    a[q*4+3] -= cc0*u0.w + cc1*u1.w + cc2*u2.w + cc3*u3.w;
                }
                if (t < 15) {
                    int jk2 = jk + 4, chk2 = chk;
                    if (jk2 == 12) { jk2 = 0; chk2 = chk + 1; }
                    if (ch == chk2) {
                        float4* fb = (float4*)&sfball[nb][row][0];
                        fb[0] = make_float4(a[0], a[1], a[2], a[3]);
                        fb[1] = make_float4(a[4], a[5], a[6], a[7]);
                        fb[2] = make_float4(a[8], a[9], a[10], a[11]);
                    }
                    if (row >= k + 4 && row < k + 8) {
                        float4* pv = (float4*)&spivq[nb][row - (k + 4)][c0];
                        pv[0] = make_float4(a[0], a[1], a[2], a[3]);
                        pv[1] = make_float4(a[4], a[5], a[6], a[7]);
                        pv[2] = make_float4(a[8], a[9], a[10], a[11]);
                    }
                } else {
                    if (ch == 5) {
                        float4* fb = (float4*)&sfball[nb][row][0];
                        fb[0] = make_float4(a[0], a[1], a[2], a[3]);
                        fb[1] = make_float4(a[4], a[5], a[6], a[7]);
                        fb[2] = make_float4(a[8], a[9], a[10], a[11]);
                    }
                    if (row == 64) {
                        float4* pv = (float4*)&spivq[nb][0][c0];
                        pv[0] = make_float4(a[0], a[1], a[2], a[3]);
                        pv[1] = make_float4(a[4], a[5], a[6], a[7]);
                        pv[2] = make_float4(a[8], a[9], a[10], a[11]);
                    }
                }
            }
            __syncthreads();
            jk += 4; if (jk == 12) { jk = 0; chk++; }
        }
        if (act) {
            float rk = rcpa(spivq[0][0][64]);
            float s0 = sfball[0][row][4];
            float f  = (row == 64) ? 0.f : s0 * rk;
            const float4* pv = (const float4*)&spivq[0][0][c0];
            float4 u0 = pv[0], u1 = pv[1], u2 = pv[2];
            a[0] -= f * u0.x; a[1] -= f * u0.y; a[2]  -= f * u0.z; a[3]  -= f * u0.w;
            a[4] -= f * u1.x; a[5] -= f * u1.y; a[6]  -= f * u1.z; a[7]  -= f * u1.w;
            a[8] -= f * u2.x; a[9] -= f * u2.y; a[10] -= f * u2.z; a[11] -= f * u2.w;
        }
        if (act) {
            if (ch == 5) srhs[row] = a[5];
#pragma unroll
            for (int j = 0; j < 12; j++) if (c0 + j == row) sdiag[row] = a[j];
        }
        __syncthreads();
        if (tid < NN) sp[tid] = __fdividef(srhs[tid], sdiag[tid]);
        __syncthreads();
        if (s == NSTEPS - 1 && tid < NG) {
            int i = tid + 1;
            float accf = 0.f, pi = sp[i];
            for (int j = 0; j < NN; j++) accf += fabsf(sC[i * SW + j] * (pi - sp[j]));
            g_gflow[b * NG + tid] = accf;
        }
        __syncthreads();
        float* dhs = dh + (size_t)(s + 1) * NN * NN;
        float* qhs = qh + (size_t)s * NN * NN;
        {
            int i = tid / NN, j = tid - i * NN;
            for (int idx = tid; idx < NN * NN; idx += 416) {
                float c = sC[i * SW + j];
                float fl = c * (sp[i] - sp[j]);
                qhs[idx] = fl;
                float aab = fabsf(fl);
                float r = __fdividef(aab, 1.f + aab);
                float cn = c + 0.1f * (r - 0.1f * c);
                cn = fmaxf(cn, 0.f);
                cn = (i == j) ? 0.f : fmaxf(cn, 1e-4f);
                auxst += fabsf(cn - c);
                sC[i * SW + j] = cn;
                dhs[idx] = cn;
                j += 26; i += 6; if (j >= NN) { j -= NN; i++; }
            }
        }
    }
    __syncthreads();
    float asp = 0.f;
    {
        int i = tid / NN, j = tid - i * NN;
        for (int idx = tid; idx < NN * NN; idx += 416) {
            if (i >= 1 && j >= 1) asp += sC[i * SW + j];
            j += 26; i += 6; if (j >= NN) { j -= NN; i++; }
        }
    }
    sred[tid] = asp; __syncthreads();
    for (int st = 256; st >= 1; st >>= 1) {
        if (tid < st && tid + st < 416) sred[tid] += sred[tid + st];
        __syncthreads();
    }
    if (tid == 0) g_auxsp[b] = sred[0];
    __syncthreads();
    sred[tid] = auxst; __syncthreads();
    for (int st = 256; st >= 1; st >>= 1) {
        if (tid < st && tid + st < 416) sred[tid] += sred[tid + st];
        __syncthreads();
    }
    if (tid == 0) g_auxst[b] = sred[0];
    __syncthreads();
    if (tid < NG) {
        int i = tid + 1;
        float rs = 0.f;
        for (int j = 1; j < NN; j++) rs += sC[i * SW + j];
        srhs[tid] = fmaxf(rs, 1e-6f);
    }
    __syncthreads();
    float* rt = out + OFF_RT + (size_t)b * NG * NG;
    {
        int i = tid / NG, j = tid - i * NG;
        for (int idx = tid; idx < NG * NG; idx += 416) {
            rt[idx] = __fdividef(sC[(i + 1) * SW + (j + 1)], srhs[i]);
            j += 32; i += 6; if (j >= NG) { j -= NG; i++; }
        }
    }
}

// ============ K6: scores, gid, top-k masks (+aux scalars in block 0) ======
__global__ void __launch_bounds__(576) k_post(const float* __restrict__ local,
                                              float* __restrict__ out) {
    __shared__ float sc[1024];
    __shared__ float sts[PP];
    __shared__ float sng[NG];
    __shared__ float red[1024];
    __shared__ float sms[2];
    __shared__ int scnt;
    __shared__ unsigned char smask[PP];
    int b = blockIdx.x, tid = threadIdx.x;

    if (b == 0 && tid < 32) {
        float v1 = g_auxsp[tid] + g_auxsp[tid + 32];
        float v2 = g_auxst[tid] + g_auxst[tid + 32];
#pragma unroll
        for (int off = 16; off >= 1; off >>= 1) {
            v1 += __shfl_down_sync(0xffffffffu, v1, off);
            v2 += __shfl_down_sync(0xffffffffu, v2, off);
        }
        if (tid == 0) { out[OFF_AS] = v1 / (float)BB; out[OFF_AST] = v2 / (float)BB; }
    }

    if (tid < NG) red[tid] = g_gflow[b * NG + tid];
    __syncthreads();
    if (tid == 0) {
        float m = 0.f;
        for (int i = 0; i < NG; i++) m += red[i];
        m /= (float)NG;
        float v = 0.f;
        for (int i = 0; i < NG; i++) { float d = red[i] - m; v += d * d; }
        float sd = fmaxf(sqrtf(v / 63.f), 1e-6f);
        sms[0] = m; sms[1] = sd;
    }
    __syncthreads();
    if (tid < NG) sng[tid] = (red[tid] - sms[0]) / sms[1];
    __syncthreads();

    float lv = local[b * PP + tid];
    red[tid] = lv; if (tid < 448) red[PP + tid] = 0.f;
    __syncthreads();
    for (int st = 512; st >= 1; st >>= 1) {
        if (tid < st) red[tid] += red[tid + st];
        __syncthreads();
    }
    float lmean = red[0] / (float)PP;
    __syncthreads();
    float dlv = lv - lmean;
    red[tid] = dlv * dlv; if (tid < 448) red[PP + tid] = 0.f;
    __syncthreads();
    for (int st = 512; st >= 1; st >>= 1) {
        if (tid < st) red[tid] += red[tid + st];
        __syncthreads();
    }
    float lstd = fmaxf(sqrtf(red[0] / 575.f), 1e-6f);
    __syncthreads();
    float nloc = dlv / lstd;

    int gid = ((tid / 24) / 3) * 8 + ((tid % 24) / 3);
    float gs = sng[gid];
    float ts = gs + 0.5f * nloc;
    out[OFF_GID + b * PP + tid] = (float)gid;
    out[OFF_GS  + b * PP + tid] = gs;
    sts[tid] = ts;
    sc[tid] = ts; if (tid < 448) sc[PP + tid] = -3.4e38f;
    if (tid == 0) scnt = 0;
    __syncthreads();
    for (int k = 2; k <= 1024; k <<= 1)
        for (int j = k >> 1; j > 0; j >>= 1) {
            for (int i = tid; i < 1024; i += 576) {
                int ixj = i ^ j;
                if (ixj > i) {
                    float x = sc[i], y = sc[ixj];
                    if (((i & k) == 0) == (x > y)) { sc[i] = y; sc[ixj] = x; }
                }
            }
            __syncthreads();
        }
    float thr = sc[1024 - 288];
    int m = (ts > thr) ? 1 : 0;
    if (m) atomicAdd(&scnt, 1);
    smask[tid] = (unsigned char)m;
    __syncthreads();
    if (tid == 0) {
        int rem = 288 - scnt;
        for (int t = 0; t < PP && rem > 0; t++)
            if (!smask[t] && sts[t] == thr) { smask[t] = 1; rem--; }
    }
    __syncthreads();
    float mv = smask[tid] ? 1.f : 0.f;
    out[OFF_PKEEP + b * PP + tid] = mv;
    out[OFF_KEEP + b * (PP + 1) + 1 + tid] = mv;
    if (tid == 0) out[OFF_KEEP + b * (PP + 1)] = 1.f;
}

// ============ launcher ====================================================
extern "C" void kernel_launch(void* const* d_in, const int* in_sizes, int n_in,
                              void* d_out, int out_size) {
    (void)in_sizes; (void)n_in; (void)out_size;
    const float* tokens = (const float*)d_in[0];
    const float* cls    = (const float*)d_in[1];
    const float* Wm     = (const float*)d_in[2];
    const float* local  = (const float*)d_in[3];
    float* out = (float*)d_out;

    cudaFuncSetAttribute(k_gemm_mma,
                         cudaFuncAttributeMaxDynamicSharedMemorySize, GEMM_SMEM);
    cudaFuncSetAttribute(k_gram_mma,
                         cudaFuncAttributeMaxDynamicSharedMemorySize, GEMM_SMEM);

    k_nodes_cvt<<<dim3(NN, BB), 192>>>(tokens, cls);
    k_cvtB     <<<DD * DD / 1024, 256>>>(Wm);
    k_gemm_mma <<<dim3(33, 6), 256, GEMM_SMEM>>>();
    k_gram_mma <<<dim3(BB, 3), 256, GEMM_SMEM>>>();
    k_dyn      <<<BB, 416>>>(out);
    k_post     <<<BB, 576>>>(local, out);
}

// round 16
// speedup vs baseline: 1.0327x; 1.0327x over previous
#include <cuda_runtime.h>
#include <cuda_bf16.h>
#include <math.h>
#include <stdint.h>

// ---------------- problem constants ----------------
#define BB 64
#define PP 576
#define DD 768
#define NG 64
#define NN 65
#define NSTEPS 8
#define SW 72              // padded dyn matrix stride (6 chunks x 12)
#define ROWS_PAD 4224      // 4160 rows + pad (33 x 128)
#define KTOT 1536          // [hi | lo] bf16 columns
#define NSLAB64 36         // gemm k64 slabs
#define NSLAB_G 12         // gram k64 slabs per cross-term
#define GSTRIDE 72         // smem row stride (elements)
#define TILE_ELEMS (128 * GSTRIDE)
#define NSTAGE 3
#define GEMM_SMEM (NSTAGE * 2 * TILE_ELEMS * 2)   // 110592 B

// ---------------- output layout (float32, concatenated) ----
#define OFF_KEEP  0
#define OFF_PKEEP 36928
#define OFF_GID   73792
#define OFF_GS    110656
#define OFF_DH    147520
#define OFF_QH    2581120
#define OFF_RT    4744320
#define OFF_AS    5006464
#define OFF_AST   5006465

// ---------------- scratch (static device globals) ----------
__device__ __nv_bfloat16 g_abf[ROWS_PAD * KTOT];      // 13 MB (pad rows stay 0)
__device__ __nv_bfloat16 g_bbf[DD * KTOT];            // 2.3 MB
__device__ __nv_bfloat16 g_pbf[BB * 128 * KTOT];      // 25 MB proj hi/lo, pad rows 0
__device__ float g_gramp[BB * 2 * NN * NN];           // hh, hl (lh = hl^T)
__device__ float g_gflow[BB * NG];
__device__ float g_auxsp[BB];
__device__ float g_auxst[BB];

// ---------------- helpers ----------------
__device__ __forceinline__ uint32_t smem_u32(const void* p) {
    uint32_t a;
    asm("{ .reg .u64 t; cvta.to.shared.u64 t, %1; cvt.u32.u64 %0, t; }"
        : "=r"(a) : "l"(p));
    return a;
}
__device__ __forceinline__ void ldsm_x4(uint32_t* r, uint32_t addr) {
    asm volatile("ldmatrix.sync.aligned.m8n8.x4.shared.b16 {%0,%1,%2,%3}, [%4];"
                 : "=r"(r[0]), "=r"(r[1]), "=r"(r[2]), "=r"(r[3]) : "r"(addr));
}
__device__ __forceinline__ void mma16816(float* d, const uint32_t* a,
                                         uint32_t b0, uint32_t b1) {
    asm volatile("mma.sync.aligned.m16n8k16.row.col.f32.bf16.bf16.f32 "
                 "{%0,%1,%2,%3}, {%4,%5,%6,%7}, {%8,%9}, {%0,%1,%2,%3};"
                 : "+f"(d[0]), "+f"(d[1]), "+f"(d[2]), "+f"(d[3])
                 : "r"(a[0]), "r"(a[1]), "r"(a[2]), "r"(a[3]), "r"(b0), "r"(b1));
}
__device__ __forceinline__ void cp16(uint32_t saddr, const void* g) {
    asm volatile("cp.async.cg.shared.global [%0], [%1], 16;"
                 :: "r"(saddr), "l"(g));
}
#define CP_COMMIT() asm volatile("cp.async.commit_group;" ::: "memory")
#define CP_WAIT1()  asm volatile("cp.async.wait_group 1;" ::: "memory")
#define CP_WAIT0()  asm volatile("cp.async.wait_group 0;" ::: "memory")
__device__ __forceinline__ uint32_t pkbf(__nv_bfloat16 a, __nv_bfloat16 b) {
    return (uint32_t)__bfloat16_as_ushort(a) |
           ((uint32_t)__bfloat16_as_ushort(b) << 16);
}
__device__ __forceinline__ float rcpa(float x) {
    float r; asm("rcp.approx.f32 %0, %1;" : "=f"(r) : "f"(x)); return r;
}

// ============ K1: fused group pooling + hi/lo bf16 split ==================
__global__ void k_nodes_cvt(const float* __restrict__ tokens,
                            const float* __restrict__ cls) {
    int n = blockIdx.x, b = blockIdx.y, t = threadIdx.x;
    float4 s;
    if (n == 0) {
        s = ((const float4*)&cls[b * DD])[t];
    } else {
        int g = n - 1, gr = g >> 3, gc = g & 7;
        s = make_float4(0.f, 0.f, 0.f, 0.f);
#pragma unroll
        for (int rr = 0; rr < 3; rr++)
#pragma unroll
            for (int cc = 0; cc < 3; cc++) {
                int p = (gr * 3 + rr) * 24 + gc * 3 + cc;
                float4 v = ((const float4*)&tokens[(b * PP + p) * DD])[t];
                s.x += v.x; s.y += v.y; s.z += v.z; s.w += v.w;
            }
        const float inv9 = 1.f / 9.f;
        s.x *= inv9; s.y *= inv9; s.z *= inv9; s.w *= inv9;
    }
    __nv_bfloat16 h0 = __float2bfloat16(s.x), h1 = __float2bfloat16(s.y);
    __nv_bfloat16 h2 = __float2bfloat16(s.z), h3 = __float2bfloat16(s.w);
    __nv_bfloat16 l0 = __float2bfloat16(s.x - __bfloat162float(h0));
    __nv_bfloat16 l1 = __float2bfloat16(s.y - __bfloat162float(h1));
    __nv_bfloat16 l2 = __float2bfloat16(s.z - __bfloat162float(h2));
    __nv_bfloat16 l3 = __float2bfloat16(s.w - __bfloat162float(h3));
    size_t row = (size_t)(b * NN + n);
    int col = t * 4;
    *(uint2*)&g_abf[row * KTOT + col]      = make_uint2(pkbf(h0, h1), pkbf(h2, h3));
    *(uint2*)&g_abf[row * KTOT + DD + col] = make_uint2(pkbf(l0, l1), pkbf(l2, l3));
}

// ============ K2: hi/lo bf16 split of W ===================================
__global__ void __launch_bounds__(256) k_cvtB(const float* __restrict__ Wm) {
    int lin = (blockIdx.x * 256 + threadIdx.x) * 4;   // [0, 768*768)
    int row = lin / DD, col = lin - row * DD;
    float4 v = *(const float4*)&Wm[lin];
    __nv_bfloat16 h0 = __float2bfloat16(v.x), h1 = __float2bfloat16(v.y);
    __nv_bfloat16 h2 = __float2bfloat16(v.z), h3 = __float2bfloat16(v.w);
    __nv_bfloat16 l0 = __float2bfloat16(v.x - __bfloat162float(h0));
    __nv_bfloat16 l1 = __float2bfloat16(v.y - __bfloat162float(h1));
    __nv_bfloat16 l2 = __float2bfloat16(v.z - __bfloat162float(h2));
    __nv_bfloat16 l3 = __float2bfloat16(v.w - __bfloat162float(h3));
    uint2* dh = (uint2*)&g_bbf[(size_t)row * KTOT + col];
    uint2* dl = (uint2*)&g_bbf[(size_t)row * KTOT + DD + col];
    *dh = make_uint2(pkbf(h0, h1), pkbf(h2, h3));
    *dl = make_uint2(pkbf(l0, l1), pkbf(l2, l3));
}

// ============ K3: mma.sync bf16 GEMM — epilogue emits hi/lo bf16 ==========
__global__ void __launch_bounds__(256, 2) k_gemm_mma() {
    extern __shared__ __align__(16) uint16_t smem[];
    int tid = threadIdx.x, wid = tid >> 5, lane = tid & 31;
    int mbase = blockIdx.x * 128, nbase = blockIdx.y * 128;
    int wm = (wid & 3) * 32, wn = (wid >> 2) * 64;

    uint32_t base = smem_u32(smem);
    int lr[4], lc[4]; uint32_t lso[4];
#pragma unroll
    for (int i = 0; i < 4; i++) {
        int lin = tid + i * 256;
        lr[i] = lin >> 3; lc[i] = (lin & 7) * 8;
        lso[i] = (uint32_t)(lr[i] * GSTRIDE + lc[i]) * 2;
    }
    const __nv_bfloat16* gA = g_abf + (size_t)mbase * KTOT;
    const __nv_bfloat16* gB = g_bbf + (size_t)nbase * KTOT;

    auto akf = [](int s) { return (s < 12 ? s * 64 : (s < 24 ? (s - 12) * 64 : DD + (s - 24) * 64)); };
    auto bkf = [](int s) { return (s < 12 ? s * 64 : (s < 24 ? DD + (s - 12) * 64 : (s - 24) * 64)); };

    uint32_t aOff = (uint32_t)((wm + (lane & 15)) * 144 + (lane >> 4) * 16);
    uint32_t bOff = (uint32_t)((wn + (lane & 7) + ((lane >> 4) << 3)) * 144 +
                               ((lane >> 3) & 1) * 16);

#pragma unroll
    for (int p = 0; p < 2; p++) {
        int ak = akf(p), bk = bkf(p);
        uint32_t sa = base + (uint32_t)p * (2 * TILE_ELEMS * 2);
        uint32_t sb = sa + TILE_ELEMS * 2;
#pragma unroll
        for (int i = 0; i < 4; i++) {
            cp16(sa + lso[i], gA + (size_t)lr[i] * KTOT + ak + lc[i]);
            cp16(sb + lso[i], gB + (size_t)lr[i] * KTOT + bk + lc[i]);
        }
        CP_COMMIT();
    }

    float acc[2][8][4];
#pragma unroll
    for (int mi = 0; mi < 2; mi++)
#pragma unroll
        for (int nj = 0; nj < 8; nj++)
#pragma unroll
            for (int q = 0; q < 4; q++) acc[mi][nj][q] = 0.f;

    int stg = 0, stg2 = 2;
    for (int s = 0; s < NSLAB64; s++) {
        if (s < NSLAB64 - 1) CP_WAIT1(); else CP_WAIT0();
        __syncthreads();
        if (s + 2 < NSLAB64) {
            int ak = akf(s + 2), bk = bkf(s + 2);
            uint32_t sa = base + (uint32_t)stg2 * (2 * TILE_ELEMS * 2);
            uint32_t sb = sa + TILE_ELEMS * 2;
#pragma unroll
            for (int i = 0; i < 4; i++) {
                cp16(sa + lso[i], gA + (size_t)lr[i] * KTOT + ak + lc[i]);
                cp16(sb + lso[i], gB + (size_t)lr[i] * KTOT + bk + lc[i]);
            }
            CP_COMMIT();
        }
        uint32_t sa = base + (uint32_t)stg * (2 * TILE_ELEMS * 2) + aOff;
        uint32_t sb = base + (uint32_t)stg * (2 * TILE_ELEMS * 2) + TILE_ELEMS * 2 + bOff;
#pragma unroll
        for (int kk = 0; kk < 4; kk++) {
            uint32_t a[2][4], b[4][4];
#pragma unroll
            for (int mi = 0; mi < 2; mi++)
                ldsm_x4(a[mi], sa + mi * 2304 + kk * 32);
#pragma unroll
            for (int nb = 0; nb < 4; nb++)
                ldsm_x4(b[nb], sb + nb * 2304 + kk * 32);
#pragma unroll
            for (int mi = 0; mi < 2; mi++)
#pragma unroll
                for (int nj = 0; nj < 8; nj++)
                    mma16816(acc[mi][nj], a[mi],
                             b[nj >> 1][(nj & 1) * 2], b[nj >> 1][(nj & 1) * 2 + 1]);
        }
        stg = (stg == 2) ? 0 : stg + 1;
        stg2 = (stg2 == 2) ? 0 : stg2 + 1;
    }

    // epilogue: hi/lo bf16 into batch-padded g_pbf (rows 65..127 stay zero)
    int cbase = nbase + wn + (lane & 3) * 2;
#pragma unroll
    for (int mi = 0; mi < 2; mi++)
#pragma unroll
        for (int rr = 0; rr < 2; rr++) {
            int gr = mbase + wm + (lane >> 2) + mi * 16 + rr * 8;
            if (gr < BB * NN) {
                int b = gr / NN;
                int r = gr - b * NN;
                __nv_bfloat16* dst = g_pbf + (size_t)b * (128 * KTOT) + (size_t)r * KTOT;
#pragma unroll
                for (int nj = 0; nj < 8; nj++) {
                    float v0 = acc[mi][nj][rr * 2 + 0];
                    float v1 = acc[mi][nj][rr * 2 + 1];
                    __nv_bfloat16 h0 = __float2bfloat16(v0);
                    __nv_bfloat16 h1 = __float2bfloat16(v1);
                    __nv_bfloat16 l0 = __float2bfloat16(v0 - __bfloat162float(h0));
                    __nv_bfloat16 l1 = __float2bfloat16(v1 - __bfloat162float(h1));
                    int cn = cbase + nj * 8;
                    *(uint32_t*)&dst[cn]      = pkbf(h0, h1);
                    *(uint32_t*)&dst[DD + cn] = pkbf(l0, l1);
                }
            }
        }
}

// ============ K4: tensor-core Gram partials (hh and hl; lh = hl^T) ========
// grid (64, 2), block 256. A = hi always; B = hi (sterm 0) or lo (sterm 1).
__global__ void __launch_bounds__(256, 2) k_gram_mma() {
    extern __shared__ __align__(16) uint16_t smem[];
    int tid = threadIdx.x, wid = tid >> 5, lane = tid & 31;
    int b = blockIdx.x, sterm = blockIdx.y;
    int bbase = (sterm == 1) ? DD : 0;
    int wm = (wid & 3) * 32, wn = (wid >> 2) * 64;

    uint32_t base = smem_u32(smem);
    int lr[4], lc[4]; uint32_t lso[4];
#pragma unroll
    for (int i = 0; i < 4; i++) {
        int lin = tid + i * 256;
        lr[i] = lin >> 3; lc[i] = (lin & 7) * 8;
        lso[i] = (uint32_t)(lr[i] * GSTRIDE + lc[i]) * 2;
    }
    const __nv_bfloat16* gX = g_pbf + (size_t)b * (128 * KTOT);

    uint32_t aOff = (uint32_t)((wm + (lane & 15)) * 144 + (lane >> 4) * 16);
    uint32_t bOff = (uint32_t)((wn + (lane & 7) + ((lane >> 4) << 3)) * 144 +
                               ((lane >> 3) & 1) * 16);

#pragma unroll
    for (int p = 0; p < 2; p++) {
        int ak = p * 64, bk = bbase + p * 64;
        uint32_t sa = base + (uint32_t)p * (2 * TILE_ELEMS * 2);
        uint32_t sb = sa + TILE_ELEMS * 2;
#pragma unroll
        for (int i = 0; i < 4; i++) {
            cp16(sa + lso[i], gX + (size_t)lr[i] * KTOT + ak + lc[i]);
            cp16(sb + lso[i], gX + (size_t)lr[i] * KTOT + bk + lc[i]);
        }
        CP_COMMIT();
    }

    float acc[2][8][4];
#pragma unroll
    for (int mi = 0; mi < 2; mi++)
#pragma unroll
        for (int nj = 0; nj < 8; nj++)
#pragma unroll
            for (int q = 0; q < 4; q++) acc[mi][nj][q] = 0.f;

    int stg = 0, stg2 = 2;
    for (int s = 0; s < NSLAB_G; s++) {
        if (s < NSLAB_G - 1) CP_WAIT1(); else CP_WAIT0();
        __syncthreads();
        if (s + 2 < NSLAB_G) {
            int ak = (s + 2) * 64, bk = bbase + (s + 2) * 64;
            uint32_t sa = base + (uint32_t)stg2 * (2 * TILE_ELEMS * 2);
            uint32_t sb = sa + TILE_ELEMS * 2;
#pragma unroll
            for (int i = 0; i < 4; i++) {
                cp16(sa + lso[i], gX + (size_t)lr[i] * KTOT + ak + lc[i]);
                cp16(sb + lso[i], gX + (size_t)lr[i] * KTOT + bk + lc[i]);
            }
            CP_COMMIT();
        }
        uint32_t sa = base + (uint32_t)stg * (2 * TILE_ELEMS * 2) + aOff;
        uint32_t sb = base + (uint32_t)stg * (2 * TILE_ELEMS * 2) + TILE_ELEMS * 2 + bOff;
#pragma unroll
        for (int kk = 0; kk < 4; kk++) {
            uint32_t a[2][4], bq[4][4];
#pragma unroll
            for (int mi = 0; mi < 2; mi++)
                ldsm_x4(a[mi], sa + mi * 2304 + kk * 32);
#pragma unroll
            for (int nb = 0; nb < 4; nb++)
                ldsm_x4(bq[nb], sb + nb * 2304 + kk * 32);
#pragma unroll
            for (int mi = 0; mi < 2; mi++)
#pragma unroll
                for (int nj = 0; nj < 8; nj++)
                    mma16816(acc[mi][nj], a[mi],
                             bq[nj >> 1][(nj & 1) * 2], bq[nj >> 1][(nj & 1) * 2 + 1]);
        }
        stg = (stg == 2) ? 0 : stg + 1;
        stg2 = (stg2 == 2) ? 0 : stg2 + 1;
    }

    float* gp = &g_gramp[(size_t)(b * 2 + sterm) * (NN * NN)];
    int cb = wn + (lane & 3) * 2;
#pragma unroll
    for (int mi = 0; mi < 2; mi++)
#pragma unroll
        for (int rr = 0; rr < 2; rr++) {
            int r = wm + (lane >> 2) + mi * 16 + rr * 8;
            if (r < NN) {
#pragma unroll
                for (int nj = 0; nj < 8; nj++) {
                    int c = cb + nj * 8;
                    if (c < NN)     gp[r * NN + c]     = acc[mi][nj][rr * 2 + 0];
                    if (c + 1 < NN) gp[r * NN + c + 1] = acc[mi][nj][rr * 2 + 1];
                }
            }
        }
}

// ============ K5: C0 + dynamics — quad-pivot Gauss-Jordan =================
__global__ void __launch_bounds__(416) k_dyn(float* __restrict__ out) {
    __shared__ __align__(16) float sC[NN * SW];
    __shared__ __align__(16) float spivq[2][4][SW + 4];
    __shared__ __align__(16) float sfball[2][NN][12];
    __shared__ float sp[NN];
    __shared__ float spart[NN * 6];
    __shared__ float sdiag[NN], srhs[NN];
    __shared__ float sinv[NN];
    __shared__ float sred[512];

    int b = blockIdx.x, tid = threadIdx.x;
    int row = tid / 6, ch = tid - row * 6, c0 = ch * 12;
    bool act = (tid < 390);
    const float* gp = &g_gramp[(size_t)b * 2 * NN * NN];   // [hh | hl]
    float* dh = out + OFF_DH + (size_t)b * 9 * NN * NN;
    float* qh = out + OFF_QH + (size_t)b * 8 * NN * NN;

    for (int idx = tid; idx < NN * SW; idx += 416) sC[idx] = 0.f;
    if (tid < NN) {
        int d = tid * NN + tid;
        float g = gp[d] + 2.f * gp[NN * NN + d];
        sinv[tid] = rsqrtf(g);
    }
    __syncthreads();
    {
        int i = tid / NN, j = tid - i * NN;
        for (int idx = tid; idx < NN * NN; idx += 416) {
            float c = 0.f;
            if (i != j) {
                float g = gp[idx] + gp[NN * NN + idx] + gp[NN * NN + j * NN + i];
                float dot = g * sinv[i] * sinv[j];
                float d2 = fmaxf(2.f - 2.f * dot, 0.f);
                c = fmaxf(__expf(-d2), 1e-4f);
            }
            sC[i * SW + j] = c;
            dh[idx] = c;
            j += 26; i += 6; if (j >= NN) { j -= NN; i++; }
        }
    }
    float auxst = 0.f;

    for (int s = 0; s < NSTEPS; s++) {
        __syncthreads();
        if (act) {
            const float4* cr = (const float4*)&sC[row * SW + c0];
            float4 v0 = cr[0], v1 = cr[1], v2 = cr[2];
            spart[row * 6 + ch] = ((v0.x + v0.y) + (v0.z + v0.w))
                                + ((v1.x + v1.y) + (v1.z + v1.w))
                                + ((v2.x + v2.y) + (v2.z + v2.w));
        }
        __syncthreads();
        float a[12];
        if (act) {
            // own-row degree: 6 broadcast LDS (no sdeg phase/barrier)
            float dg = spart[row * 6 + 0] + spart[row * 6 + 1] + spart[row * 6 + 2]
                     + spart[row * 6 + 3] + spart[row * 6 + 4] + spart[row * 6 + 5]
                     + 1e-4f;
            const float4* cr = (const float4*)&sC[row * SW + c0];
            float4 v0 = cr[0], v1 = cr[1], v2 = cr[2];
            a[0] = -v0.x; a[1] = -v0.y; a[2]  = -v0.z; a[3]  = -v0.w;
            a[4] = -v1.x; a[5] = -v1.y; a[6]  = -v1.z; a[7]  = -v1.w;
            a[8] = -v2.x; a[9] = -v2.y; a[10] = -v2.z; a[11] = -v2.w;
            if (ch == 5) a[5] = (row == 0) ? 1.f : (-1.f / 64.f);   // col 65 = rhs
#pragma unroll
            for (int j = 0; j < 12; j++) if (c0 + j == row) a[j] = dg;
            if (ch == 0) {
                float4* fb = (float4*)&sfball[0][row][0];
                fb[0] = make_float4(a[0], a[1], a[2], a[3]);
                fb[1] = make_float4(a[4], a[5], a[6], a[7]);
                fb[2] = make_float4(a[8], a[9], a[10], a[11]);
            }
            if (row < 4) {
                float4* pv = (float4*)&spivq[0][row][c0];
                pv[0] = make_float4(a[0], a[1], a[2], a[3]);
                pv[1] = make_float4(a[4], a[5], a[6], a[7]);
                pv[2] = make_float4(a[8], a[9], a[10], a[11]);
            }
        }
        __syncthreads();
        int jk = 0, chk = 0;
        for (int t = 0; t < 16; t++) {
            int k = 4 * t;
            int pb = t & 1, nb = pb ^ 1;
            if (act) {
                float m01 = spivq[pb][0][k+1], m02 = spivq[pb][0][k+2], m03 = spivq[pb][0][k+3];
                float m10 = spivq[pb][1][k],   m11 = spivq[pb][1][k+1], m12 = spivq[pb][1][k+2], m13 = spivq[pb][1][k+3];
                float m20 = spivq[pb][2][k],   m21 = spivq[pb][2][k+1], m22 = spivq[pb][2][k+2], m23 = spivq[pb][2][k+3];
                float m30 = spivq[pb][3][k],   m31 = spivq[pb][3][k+1], m32 = spivq[pb][3][k+2], m33 = spivq[pb][3][k+3];
                float r0 = rcpa(spivq[pb][0][k]);
                float g10 = m10 * r0;
                float m11p = __fmaf_rn(-g10, m01, m11);
                float m12p = __fmaf_rn(-g10, m02, m12);
                float m13p = __fmaf_rn(-g10, m03, m13);
                float g20 = m20 * r0;
                float m21p = __fmaf_rn(-g20, m01, m21);
                float m22p = __fmaf_rn(-g20, m02, m22);
                float m23p = __fmaf_rn(-g20, m03, m23);
                float g30 = m30 * r0;
                float m31p = __fmaf_rn(-g30, m01, m31);
                float m32p = __fmaf_rn(-g30, m02, m32);
                float m33p = __fmaf_rn(-g30, m03, m33);
                float r1 = rcpa(m11p);
                float g21 = m21p * r1;
                float m22q = __fmaf_rn(-g21, m12p, m22p);
                float m23q = __fmaf_rn(-g21, m13p, m23p);
                float g31 = m31p * r1;
                float m32q = __fmaf_rn(-g31, m12p, m32p);
                float m33q = __fmaf_rn(-g31, m13p, m33p);
                float r2 = rcpa(m22q);
                float g32 = m32q * r2;
                float m33r = __fmaf_rn(-g32, m23q, m33q);
                float r3 = rcpa(m33r);
                float s0 = sfball[pb][row][jk];
                float s1 = sfball[pb][row][jk + 1];
                float s2 = sfball[pb][row][jk + 2];
                float s3 = sfball[pb][row][jk + 3];
                float f0 = (row == k) ? 0.f : s0 * r0;
                float s1p = __fmaf_rn(-f0, m01, s1);
                float f1 = (row == k + 1) ? 0.f : s1p * r1;
                float s2p = s2 - f0 * m02 - f1 * m12p;
                float f2 = (row == k + 2) ? 0.f : s2p * r2;
                float s3p = s3 - f0 * m03 - f1 * m13p - f2 * m23q;
                float f3 = (row == k + 3) ? 0.f : s3p * r3;
                float cc3 = f3;
                float cc2 = __fmaf_rn(-cc3, g32, f2);
                float cc1 = f1 - cc2 * g21 - cc3 * g31;
                float cc0 = f0 - cc1 * g10 - cc2 * g20 - cc3 * g30;
                const float4* P0 = (const float4*)&spivq[pb][0][c0];
                const float4* P1 = (const float4*)&spivq[pb][1][c0];
                const float4* P2 = (const float4*)&spivq[pb][2][c0];
                const float4* P3 = (const float4*)&spivq[pb][3][c0];
#pragma unroll
                for (int q = 0; q < 3; q++) {
                    float4 u0 = P0[q], u1 = P1[q], u2 = P2[q], u3 = P3[q];
                    a[q*4+0] -= cc0*u0.x + cc1*u1.x + cc2*u2.x + cc3*u3.x;
                    a[q*4+1] -= cc0*u0.y + cc1*u1.y + cc2*u2.y + cc3*u3.y;
                    a[q*4+2] -= cc0*u0.z + cc1*u1.z + cc2*u2.z + cc3*u3.z;
                    a[q*4+3] -= cc0*u0.w + cc1*u1.w + cc2*u2.w + cc3*u3.w;
                }
                if (t < 15) {
                    int jk2 = jk + 4, chk2 = chk;
                    if (jk2 == 12) { jk2 = 0; chk2 = chk + 1; }
                    if (ch == chk2) {
                        float4* fb = (float4*)&sfball[nb][row][0];
                        fb[0] = make_float4(a[0], a[1], a[2], a[3]);
                        fb[1] = make_float4(a[4], a[5], a[6], a[7]);
                        fb[2] = make_float4(a[8], a[9], a[10], a[11]);
                    }
                    if (row >= k + 4 && row < k + 8) {
                        float4* pv = (float4*)&spivq[nb][row - (k + 4)][c0];
                        pv[0] = make_float4(a[0], a[1], a[2], a[3]);
                        pv[1] = make_float4(a[4], a[5], a[6], a[7]);
                        pv[2] = make_float4(a[8], a[9], a[10], a[11]);
                    }
                } else {
                    if (ch == 5) {
                        float4* fb = (float4*)&sfball[nb][row][0];
                        fb[0] = make_float4(a[0], a[1], a[2], a[3]);
                        fb[1] = make_float4(a[4], a[5], a[6], a[7]);
                        fb[2] = make_float4(a[8], a[9], a[10], a[11]);
                    }
                    if (row == 64) {
                        float4* pv = (float4*)&spivq[nb][0][c0];
                        pv[0] = make_float4(a[0], a[1], a[2], a[3]);
                        pv[1] = make_float4(a[4], a[5], a[6], a[7]);
                        pv[2] = make_float4(a[8], a[9], a[10], a[11]);
                    }
                }
            }
            __syncthreads();
            jk += 4; if (jk == 12) { jk = 0; chk++; }
        }
        if (act) {
            float rk = rcpa(spivq[0][0][64]);
            float s0 = sfball[0][row][4];
            float f  = (row == 64) ? 0.f : s0 * rk;
            const float4* pv = (const float4*)&spivq[0][0][c0];
            float4 u0 = pv[0], u1 = pv[1], u2 = pv[2];
            a[0] -= f * u0.x; a[1] -= f * u0.y; a[2]  -= f * u0.z; a[3]  -= f * u0.w;
            a[4] -= f * u1.x; a[5] -= f * u1.y; a[6]  -= f * u1.z; a[7]  -= f * u1.w;
            a[8] -= f * u2.x; a[9] -= f * u2.y; a[10] -= f * u2.z; a[11] -= f * u2.w;
        }
        if (act) {
            if (ch == 5) srhs[row] = a[5];
#pragma unroll
            for (int j = 0; j < 12; j++) if (c0 + j == row) sdiag[row] = a[j];
        }
        __syncthreads();
        if (tid < NN) sp[tid] = __fdividef(srhs[tid], sdiag[tid]);
        __syncthreads();
        if (s == NSTEPS - 1 && tid < NG) {
            int i = tid + 1;
            float accf = 0.f, pi = sp[i];
            for (int j = 0; j < NN; j++) accf += fabsf(sC[i * SW + j] * (pi - sp[j]));
            g_gflow[b * NG + tid] = accf;
        }
        __syncthreads();
        float* dhs = dh + (size_t)(s + 1) * NN * NN;
        float* qhs = qh + (size_t)s * NN * NN;
        {
            int i = tid / NN, j = tid - i * NN;
            for (int idx = tid; idx < NN * NN; idx += 416) {
                float c = sC[i * SW + j];
                float fl = c * (sp[i] - sp[j]);
                qhs[idx] = fl;
                float aab = fabsf(fl);
                float r = __fdividef(aab, 1.f + aab);
                float cn = c + 0.1f * (r - 0.1f * c);
                cn = fmaxf(cn, 0.f);
                cn = (i == j) ? 0.f : fmaxf(cn, 1e-4f);
                auxst += fabsf(cn - c);
                sC[i * SW + j] = cn;
                dhs[idx] = cn;
                j += 26; i += 6; if (j >= NN) { j -= NN; i++; }
            }
        }
    }
    __syncthreads();
    float asp = 0.f;
    {
        int i = tid / NN, j = tid - i * NN;
        for (int idx = tid; idx < NN * NN; idx += 416) {
            if (i >= 1 && j >= 1) asp += sC[i * SW + j];
            j += 26; i += 6; if (j >= NN) { j -= NN; i++; }
        }
    }
    sred[tid] = asp; __syncthreads();
    for (int st = 256; st >= 1; st >>= 1) {
        if (tid < st && tid + st < 416) sred[tid] += sred[tid + st];
        __syncthreads();
    }
    if (tid == 0) g_auxsp[b] = sred[0];
    __syncthreads();
    sred[tid] = auxst; __syncthreads();
    for (int st = 256; st >= 1; st >>= 1) {
        if (tid < st && tid + st < 416) sred[tid] += sred[tid + st];
        __syncthreads();
    }
    if (tid == 0) g_auxst[b] = sred[0];
    __syncthreads();
    if (tid < NG) {
        int i = tid + 1;
        float rs = 0.f;
        for (int j = 1; j < NN; j++) rs += sC[i * SW + j];
        srhs[tid] = fmaxf(rs, 1e-6f);
    }
    __syncthreads();
    float* rt = out + OFF_RT + (size_t)b * NG * NG;
    {
        int i = tid / NG, j = tid - i * NG;
        for (int idx = tid; idx < NG * NG; idx += 416) {
            rt[idx] = __fdividef(sC[(i + 1) * SW + (j + 1)], srhs[i]);
            j += 32; i += 6; if (j >= NG) { j -= NG; i++; }
        }
    }
}

// ============ K6: scores, gid, top-k masks (+aux scalars in block 0) ======
__global__ void __launch_bounds__(576) k_post(const float* __restrict__ local,
                                              float* __restrict__ out) {
    __shared__ float sc[1024];
    __shared__ float sts[PP];
    __shared__ float sng[NG];
    __shared__ float red[1024];
    __shared__ float sms[2];
    __shared__ int scnt;
    __shared__ unsigned char smask[PP];
    int b = blockIdx.x, tid = threadIdx.x;

    if (b == 0 && tid < 32) {
        float v1 = g_auxsp[tid] + g_auxsp[tid + 32];
        float v2 = g_auxst[tid] + g_auxst[tid + 32];
#pragma unroll
        for (int off = 16; off >= 1; off >>= 1) {
            v1 += __shfl_down_sync(0xffffffffu, v1, off);
            v2 += __shfl_down_sync(0xffffffffu, v2, off);
        }
        if (tid == 0) { out[OFF_AS] = v1 / (float)BB; out[OFF_AST] = v2 / (float)BB; }
    }

    if (tid < NG) red[tid] = g_gflow[b * NG + tid];
    __syncthreads();
    if (tid == 0) {
        float m = 0.f;
        for (int i = 0; i < NG; i++) m += red[i];
        m /= (float)NG;
        float v = 0.f;
        for (int i = 0; i < NG; i++) { float d = red[i] - m; v += d * d; }
        float sd = fmaxf(sqrtf(v / 63.f), 1e-6f);
        sms[0] = m; sms[1] = sd;
    }
    __syncthreads();
    if (tid < NG) sng[tid] = (red[tid] - sms[0]) / sms[1];
    __syncthreads();

    float lv = local[b * PP + tid];
    red[tid] = lv; if (tid < 448) red[PP + tid] = 0.f;
    __syncthreads();
    for (int st = 512; st >= 1; st >>= 1) {
        if (tid < st) red[tid] += red[tid + st];
        __syncthreads();
    }
    float lmean = red[0] / (float)PP;
    __syncthreads();
    float dlv = lv - lmean;
    red[tid] = dlv * dlv; if (tid < 448) red[PP + tid] = 0.f;
    __syncthreads();
    for (int st = 512; st >= 1; st >>= 1) {
        if (tid < st) red[tid] += red[tid + st];
        __syncthreads();
    }
    float lstd = fmaxf(sqrtf(red[0] / 575.f), 1e-6f);
    __syncthreads();
    float nloc = dlv / lstd;

    int gid = ((tid / 24) / 3) * 8 + ((tid % 24) / 3);
    float gs = sng[gid];
    float ts = gs + 0.5f * nloc;
    out[OFF_GID + b * PP + tid] = (float)gid;
    out[OFF_GS  + b * PP + tid] = gs;
    sts[tid] = ts;
    sc[tid] = ts; if (tid < 448) sc[PP + tid] = -3.4e38f;
    if (tid == 0) scnt = 0;
    __syncthreads();
    for (int k = 2; k <= 1024; k <<= 1)
        for (int j = k >> 1; j > 0; j >>= 1) {
            for (int i = tid; i < 1024; i += 576) {
                int ixj = i ^ j;
                if (ixj > i) {
                    float x = sc[i], y = sc[ixj];
                    if (((i & k) == 0) == (x > y)) { sc[i] = y; sc[ixj] = x; }
                }
            }
            __syncthreads();
        }
    float thr = sc[1024 - 288];
    int m = (ts > thr) ? 1 : 0;
    if (m) atomicAdd(&scnt, 1);
    smask[tid] = (unsigned char)m;
    __syncthreads();
    if (tid == 0) {
        int rem = 288 - scnt;
        for (int t = 0; t < PP && rem > 0; t++)
            if (!smask[t] && sts[t] == thr) { smask[t] = 1; rem--; }
    }
    __syncthreads();
    float mv = smask[tid] ? 1.f : 0.f;
    out[OFF_PKEEP + b * PP + tid] = mv;
    out[OFF_KEEP + b * (PP + 1) + 1 + tid] = mv;
    if (tid == 0) out[OFF_KEEP + b * (PP + 1)] = 1.f;
}

// ============ launcher ====================================================
extern "C" void kernel_launch(void* const* d_in, const int* in_sizes, int n_in,
                              void* d_out, int out_size) {
    (void)in_sizes; (void)n_in; (void)out_size;
    const float* tokens = (const float*)d_in[0];
    const float* cls    = (const float*)d_in[1];
    const float* Wm     = (const float*)d_in[2];
    const float* local  = (const float*)d_in[3];
    float* out = (float*)d_out;

    cudaFuncSetAttribute(k_gemm_mma,
                         cudaFuncAttributeMaxDynamicSharedMemorySize, GEMM_SMEM);
    cudaFuncSetAttribute(k_gram_mma,
                         cudaFuncAttributeMaxDynamicSharedMemorySize, GEMM_SMEM);

    k_nodes_cvt<<<dim3(NN, BB), 192>>>(tokens, cls);
    k_cvtB     <<<DD * DD / 1024, 256>>>(Wm);
    k_gemm_mma <<<dim3(33, 6), 256, GEMM_SMEM>>>();
    k_gram_mma <<<dim3(BB, 2), 256, GEMM_SMEM>>>();
    k_dyn      <<<BB, 416>>>(out);
    k_post     <<<BB, 576>>>(local, out);
}